// round 6
// baseline (speedup 1.0000x reference)
#include <cuda_runtime.h>
#include <math.h>

// ---------------- problem constants ----------------
#define NE_    100000
#define NR_    200
#define STT_   512
#define ABS_   256
#define REL_   256
#define RDIM_  384
#define BB     8192
#define NCOL   406          // 6 scalar cols + 2*NR
#define GAMMA_F 12.0f

// ---------------- scratch (__device__ globals; no allocs allowed) ----------------
__device__ float g_Wc[512 * 256];          // folded e_p_emb weight  (512 KB)
__device__ float g_P[2 * BB * 256];        // e_p for s rows [0,B) and o rows [B,2B)  (16 MB)
__device__ float g_scabs[BB];              // per-row sc_abs

// ======================================================================
// Kernel 0: fold w_e (512x128) into the single real GEMM weight Wc (512x256)
//   j <  128 : Wc[k][j]   = (k<256 ?  +1 : -1) * w_e[k][j]
//   j >= 128 : Wc[k][j]   = (k<256 ?  -1 : +1) * w_e[k^256][j-128]
// ======================================================================
__global__ void k_wc(const float* __restrict__ w_e) {
    int k = blockIdx.x;        // 0..511
    int j = threadIdx.x;       // 0..255
    float v;
    if (j < 128) {
        v = w_e[k * 128 + j];
        if (k >= 256) v = -v;
    } else {
        v = w_e[(k ^ 256) * 128 + (j - 128)];
        if (k < 256) v = -v;
    }
    g_Wc[k * 256 + j] = v;
}

// ======================================================================
// Kernel 1: per row — t_emb for s and o, then sc_abs (the rotated-distance term)
// block = 256 threads, one row per block
// ======================================================================
__global__ void __launch_bounds__(256) k_gather(
    const int* __restrict__ x, int xs,
    const float* __restrict__ e_emb,
    const float* __restrict__ r_emb,
    const float* __restrict__ d_frq, const float* __restrict__ d_phi,
    const float* __restrict__ d_amp,
    const float* __restrict__ m_frq, const float* __restrict__ m_phi,
    const float* __restrict__ m_amp)
{
    __shared__ float st[256];
    __shared__ float ot[256];
    __shared__ float red8[8];

    const int b   = blockIdx.x;
    const int tid = threadIdx.x;
    const int base = b * NCOL;

    const int s_idx = x[(base + 0) * xs];
    const int r_idx = x[(base + 1) * xs];
    const int o_idx = x[(base + 2) * xs];
    const float dv  = (float)x[(base + 3) * xs];
    const float mv  = (float)x[(base + 4) * xs];

    // ---- t_emb (j = tid covers all 256 dims) ----
    {
        const int j  = tid;
        const int jm = (j < 128) ? j : (j - 128);
        // subject
        {
            const size_t e = (size_t)s_idx;
            float angd = fmaf(dv, d_frq[e * 256 + j], d_phi[e * 256 + j]);
            float angm = fmaf(mv, m_frq[e * 256 + j], m_phi[e * 256 + j]);
            float ad = d_amp[e * 128 + jm];
            float am = m_amp[e * 128 + jm];
            float v = (j < 128) ? (ad * __cosf(angd) + am * __cosf(angm))
                                : (ad * __sinf(angd) + am * __sinf(angm));
            st[j] = v;
        }
        // object
        {
            const size_t e = (size_t)o_idx;
            float angd = fmaf(dv, d_frq[e * 256 + j], d_phi[e * 256 + j]);
            float angm = fmaf(mv, m_frq[e * 256 + j], m_phi[e * 256 + j]);
            float ad = d_amp[e * 128 + jm];
            float am = m_amp[e * 128 + jm];
            float v = (j < 128) ? (ad * __cosf(angd) + am * __cosf(angm))
                                : (ad * __sinf(angd) + am * __sinf(angm));
            ot[j] = v;
        }
    }
    __syncthreads();

    // ---- sc_abs over k = 0..383 ----
    const float scale = (float)(3.141592653589793 / sqrt(6.0 / (double)(NR_ + RDIM_)));
    const size_t sb = (size_t)s_idx * 512;
    const size_t ob = (size_t)o_idx * 512;
    float sum = 0.0f;
    for (int k = tid; k < 384; k += 256) {
        float pr = r_emb[(size_t)r_idx * 384 + k] * scale;
        float sn, cs;
        __sincosf(pr, &sn, &cs);
        float re_s, im_s, re_o, im_o;
        if (k < 256) {
            re_s = e_emb[sb + k];
            im_s = e_emb[sb + 256 + k];
            re_o = e_emb[ob + k];
            im_o = e_emb[ob + 256 + k];
        } else {
            re_s = st[k - 256];  im_s = st[k - 128];
            re_o = ot[k - 256];  im_o = ot[k - 128];
        }
        float re = re_s * cs - im_s * sn - re_o;
        float im = re_s * sn + im_s * cs - im_o;
        sum += sqrtf(re * re + im * im);
    }

    // block reduce (256 threads)
    #pragma unroll
    for (int off = 16; off; off >>= 1) sum += __shfl_down_sync(0xffffffffu, sum, off);
    if ((tid & 31) == 0) red8[tid >> 5] = sum;
    __syncthreads();
    if (tid == 0) {
        float t = 0.0f;
        #pragma unroll
        for (int i = 0; i < 8; i++) t += red8[i];
        g_scabs[b] = t;
    }
}

// ======================================================================
// Kernel 2: gathered-A GEMM  P[m][j] = sum_k e_emb[idx_m][k] * Wc[k][j]
//   m in [0, 2B): m<B -> s_idx[m], else o_idx[m-B]
//   BM=128, BN=64, BK=16, 256 threads, TM=8 x TN=4 per thread
// ======================================================================
__global__ void __launch_bounds__(256) k_gemm(
    const float* __restrict__ e_emb,
    const int* __restrict__ x, int xs)
{
    __shared__ float As[16][128];   // k-major (transposed) A tile
    __shared__ float Bs[16][64];

    const int tid = threadIdx.x;
    const int bn = blockIdx.x * 64;
    const int bm = blockIdx.y * 128;
    const int tx = tid & 15;        // n
    const int ty = tid >> 4;        // m

    float acc[8][4];
    #pragma unroll
    for (int i = 0; i < 8; i++)
        #pragma unroll
        for (int j = 0; j < 4; j++) acc[i][j] = 0.0f;

    // A-load assignment: 128 rows x 16 cols = 512 float4; 2 per thread
    const int lin0 = tid,       r0 = lin0 >> 2, c0 = (lin0 & 3) << 2;
    const int lin1 = tid + 256, r1 = lin1 >> 2, c1 = (lin1 & 3) << 2;
    const int gr0 = bm + r0, gr1 = bm + r1;
    const int e0 = (gr0 < BB) ? x[(gr0 * NCOL + 0) * xs] : x[((gr0 - BB) * NCOL + 2) * xs];
    const int e1 = (gr1 < BB) ? x[(gr1 * NCOL + 0) * xs] : x[((gr1 - BB) * NCOL + 2) * xs];
    const float* a0 = e_emb + (size_t)e0 * 512 + c0;
    const float* a1 = e_emb + (size_t)e1 * 512 + c1;

    // B-load assignment: 16 rows x 64 cols = 256 float4; 1 per thread
    const int kb = tid >> 4;         // k row 0..15
    const int kc = (tid & 15) << 2;  // col 0..60

    for (int k0 = 0; k0 < 512; k0 += 16) {
        float4 va = *reinterpret_cast<const float4*>(a0 + k0);
        As[c0 + 0][r0] = va.x; As[c0 + 1][r0] = va.y;
        As[c0 + 2][r0] = va.z; As[c0 + 3][r0] = va.w;
        float4 vb = *reinterpret_cast<const float4*>(a1 + k0);
        As[c1 + 0][r1] = vb.x; As[c1 + 1][r1] = vb.y;
        As[c1 + 2][r1] = vb.z; As[c1 + 3][r1] = vb.w;
        float4 w4 = *reinterpret_cast<const float4*>(&g_Wc[(k0 + kb) * 256 + bn + kc]);
        *reinterpret_cast<float4*>(&Bs[kb][kc]) = w4;
        __syncthreads();

        #pragma unroll
        for (int k = 0; k < 16; k++) {
            float4 bv4 = *reinterpret_cast<const float4*>(&Bs[k][tx * 4]);
            float4 aa0 = *reinterpret_cast<const float4*>(&As[k][ty * 8]);
            float4 aa1 = *reinterpret_cast<const float4*>(&As[k][ty * 8 + 4]);
            float av[8] = {aa0.x, aa0.y, aa0.z, aa0.w, aa1.x, aa1.y, aa1.z, aa1.w};
            float bv[4] = {bv4.x, bv4.y, bv4.z, bv4.w};
            #pragma unroll
            for (int i = 0; i < 8; i++)
                #pragma unroll
                for (int j = 0; j < 4; j++)
                    acc[i][j] = fmaf(av[i], bv[j], acc[i][j]);
        }
        __syncthreads();
    }

    #pragma unroll
    for (int i = 0; i < 8; i++) {
        int row = bm + ty * 8 + i;
        float4 v = make_float4(acc[i][0], acc[i][1], acc[i][2], acc[i][3]);
        *reinterpret_cast<float4*>(&g_P[(size_t)row * 256 + bn + tx * 4]) = v;
    }
}

// ======================================================================
// Kernel 3: per row — e_r_emb (the sincos mainloop), sc_rel, final output
// block = 256 threads: side = tid>>7 (0:s, 1:o), d = tid&127 (freq index)
// ======================================================================
__global__ void __launch_bounds__(256) k_final(
    const int* __restrict__ x, int xs,
    const float* __restrict__ w_rp,
    float* __restrict__ out)
{
    __shared__ float tsf[400];      // c_s[200] then c_o[200] as float
    __shared__ float wsh[200];      // w_rp[r_idx] row
    __shared__ float sr[2][256];    // s_rel / o_rel
    __shared__ float red8[8];

    const int b   = blockIdx.x;
    const int tid = threadIdx.x;
    const int base = b * NCOL;
    const int r_idx = x[(base + 1) * xs];

    for (int i = tid; i < 400; i += 256) tsf[i] = (float)x[(base + 6 + i) * xs];
    for (int i = tid; i < 200; i += 256) wsh[i] = w_rp[r_idx * 200 + i];
    __syncthreads();

    const int side = tid >> 7;
    const int d    = tid & 127;
    // f_d = 10000^(-d/128) = exp2(-d * log2(10000)/128)
    const float f = exp2f(-(float)d * (13.287712379549449f / 128.0f));
    const float* ts = tsf + side * 200;

    float are = 0.0f, aim = 0.0f;
    #pragma unroll 4
    for (int n = 0; n < 200; n++) {
        float ang = ts[n] * f;
        float sn, cs;
        __sincosf(ang, &sn, &cs);
        float wn = wsh[n];
        are = fmaf(wn, cs, are);
        aim = fmaf(wn, sn, aim);
    }

    const float* Prow = g_P + (size_t)(side ? (BB + b) : b) * 256;
    sr[side][d]       = are + Prow[d];
    sr[side][128 + d] = aim + Prow[128 + d];
    __syncthreads();

    float sum = 0.0f;
    if (tid < 128) {
        float dre = sr[0][tid]       - sr[1][tid];
        float dim = sr[0][128 + tid] - sr[1][128 + tid];
        sum = sqrtf(dre * dre + dim * dim);
    }
    #pragma unroll
    for (int off = 16; off; off >>= 1) sum += __shfl_down_sync(0xffffffffu, sum, off);
    if ((tid & 31) == 0) red8[tid >> 5] = sum;
    __syncthreads();
    if (tid == 0) {
        float t = 0.0f;
        #pragma unroll
        for (int i = 0; i < 8; i++) t += red8[i];
        out[b] = GAMMA_F - (g_scabs[b] + t);
    }
}

// ======================================================================
// launcher
// ======================================================================
extern "C" void kernel_launch(void* const* d_in, const int* in_sizes, int n_in,
                              void* d_out, int out_size)
{
    const int*   x     = (const int*)  d_in[0];
    const float* e_emb = (const float*)d_in[1];
    const float* r_emb = (const float*)d_in[2];
    const float* d_frq = (const float*)d_in[3];
    const float* d_phi = (const float*)d_in[4];
    const float* d_amp = (const float*)d_in[5];
    const float* m_frq = (const float*)d_in[6];
    const float* m_phi = (const float*)d_in[7];
    const float* m_amp = (const float*)d_in[8];
    const float* w_e   = (const float*)d_in[9];
    const float* w_rp  = (const float*)d_in[10];
    float* out = (float*)d_out;

    // x may arrive as int64 reported as 2x int32 words; infer element stride.
    int xs = in_sizes[0] / (BB * NCOL);
    if (xs < 1) xs = 1;

    k_wc<<<512, 256>>>(w_e);
    k_gather<<<BB, 256>>>(x, xs, e_emb, r_emb, d_frq, d_phi, d_amp, m_frq, m_phi, m_amp);
    k_gemm<<<dim3(4, 128), 256>>>(e_emb, x, xs);
    k_final<<<BB, 256>>>(x, xs, w_rp, out);
}